// round 12
// baseline (speedup 1.0000x reference)
#include <cuda_runtime.h>
#include <cuda_bf16.h>
#include <cstdint>

#define LAMBDA_INIT_F 0.32802328f   // 0.8 - 0.6*exp(-0.3*0.8)

namespace {

constexpr int B_ = 2, N_ = 2048, H_ = 8, D_ = 64, NO_ = 1024;
constexpr int BQ = 32, BK = 64, TILES = N_ / BK;
constexpr int THREADS = 128;              // 4 warps; 2 CTAs co-resident per SM
constexpr float QSCALE = 0.125f * 1.4426950408889634f;  // 1/sqrt(64) * log2(e)

// smem layout (bytes). Row stride 128B for all bf16 tiles (64 bf16/row).
constexpr int OFF_QH = 1024;              // 64 x 128B
constexpr int OFF_QL = OFF_QH + 8192;
constexpr int OFF_KH = OFF_QL + 8192;     // 64 x 128B
constexpr int OFF_KL = OFF_KH + 8192;
constexpr int OFF_VH = OFF_KL + 8192;
constexpr int OFF_VL = OFF_VH + 8192;
constexpr int SMEM_TOTAL = OFF_VL + 8192; // 50176 B -> 2 CTAs/SM
constexpr int STG_LD = 68;                // epilogue staging stride (floats)

__device__ __forceinline__ uint32_t s2u(const void* p) {
    uint32_t a;
    asm("{ .reg .u64 t; cvta.to.shared.u64 t, %1; cvt.u32.u64 %0, t; }" : "=r"(a) : "l"(p));
    return a;
}
__device__ __forceinline__ uint32_t swz(uint32_t x) { return x ^ ((x >> 3) & 0x70); }
__device__ __forceinline__ float ex2(float x) {
    float y; asm("ex2.approx.ftz.f32 %0, %1;" : "=f"(y) : "f"(x)); return y;
}
// bf16 hi/lo split of two floats, packed bf16x2 (first value in low half)
__device__ __forceinline__ void split2(float x0, float x1, uint32_t& hp, uint32_t& lp) {
    __nv_bfloat16 h0 = __float2bfloat16(x0), h1 = __float2bfloat16(x1);
    float l0 = x0 - __bfloat162float(h0), l1 = x1 - __bfloat162float(h1);
    hp = ((uint32_t)__bfloat16_as_ushort(h1) << 16) | (uint32_t)__bfloat16_as_ushort(h0);
    __nv_bfloat162 lb = __floats2bfloat162_rn(l0, l1);
    lp = *reinterpret_cast<uint32_t*>(&lb);
}

__device__ __forceinline__ void mma16816(float* c, const uint32_t* a, const uint32_t* b) {
    asm volatile(
        "mma.sync.aligned.m16n8k16.row.col.f32.bf16.bf16.f32 "
        "{%0,%1,%2,%3}, {%4,%5,%6,%7}, {%8,%9}, {%0,%1,%2,%3};"
        : "+f"(c[0]), "+f"(c[1]), "+f"(c[2]), "+f"(c[3])
        : "r"(a[0]), "r"(a[1]), "r"(a[2]), "r"(a[3]), "r"(b[0]), "r"(b[1]));
}
__device__ __forceinline__ void ldsm4(uint32_t* r, uint32_t addr) {
    asm volatile("ldmatrix.sync.aligned.m8n8.x4.shared.b16 {%0,%1,%2,%3}, [%4];"
                 : "=r"(r[0]), "=r"(r[1]), "=r"(r[2]), "=r"(r[3]) : "r"(addr));
}
__device__ __forceinline__ void ldsm4t(uint32_t* r, uint32_t addr) {
    asm volatile("ldmatrix.sync.aligned.m8n8.x4.trans.shared.b16 {%0,%1,%2,%3}, [%4];"
                 : "=r"(r[0]), "=r"(r[1]), "=r"(r[2]), "=r"(r[3]) : "r"(addr));
}

// load 32 consecutive floats (8 x float4)
__device__ __forceinline__ void ldg32(float* d, const float* p) {
    #pragma unroll
    for (int i = 0; i < 8; ++i) {
        float4 f = reinterpret_cast<const float4*>(p)[i];
        d[4*i] = f.x; d[4*i+1] = f.y; d[4*i+2] = f.z; d[4*i+3] = f.w;
    }
}
// store 32 floats (one key row, d0..d0+31) as bf16 hi/lo into swizzled tiles
__device__ __forceinline__ void stTile(char* sm, int offH, int offL,
                                       const uint32_t* soff, const float* a) {
    #pragma unroll
    for (int j = 0; j < 8; ++j) {
        uint32_t h0, l0, h1, l1;
        split2(a[4*j],     a[4*j + 1], h0, l0);
        split2(a[4*j + 2], a[4*j + 3], h1, l1);
        *reinterpret_cast<uint2*>(sm + offH + soff[j]) = make_uint2(h0, h1);
        *reinterpret_cast<uint2*>(sm + offL + soff[j]) = make_uint2(l0, l1);
    }
}

__global__ void __launch_bounds__(THREADS, 2)
diff_attn_hmma(const float* __restrict__ Q, const float* __restrict__ K,
               const float* __restrict__ V,
               const float* __restrict__ lq1, const float* __restrict__ lk1,
               const float* __restrict__ lq2, const float* __restrict__ lk2,
               float* __restrict__ out)
{
    extern __shared__ __align__(128) char sm[];
    const uint32_t sb = s2u(sm);
    const int tid = threadIdx.x;
    const int wid = tid >> 5, lane = tid & 31;
    const int qb = blockIdx.x, h = blockIdx.y, b = blockIdx.z;
    const int qi0 = qb * BQ;

    // ---- lambda (warp 2) ----
    if (wid == 2) {
        float p1 = lq1[lane] * lk1[lane] + lq1[lane + 32] * lk1[lane + 32];
        float p2 = lq2[lane] * lk2[lane] + lq2[lane + 32] * lk2[lane + 32];
        #pragma unroll
        for (int o = 16; o; o >>= 1) {
            p1 += __shfl_xor_sync(0xffffffffu, p1, o);
            p2 += __shfl_xor_sync(0xffffffffu, p2, o);
        }
        if (lane == 0)
            *reinterpret_cast<float*>(sm) = __expf(p1) - __expf(p2) + LAMBDA_INIT_F;
    }

    // ---- stage Q (64 rows: 32 top | 32 bottom), scaled, bf16 hi/lo ----
    {
        int row = tid & 63, d0 = (tid >> 6) * 32;
        int qi = qi0 + ((row < BQ) ? row : row - BQ + NO_);
        const float4* qp = reinterpret_cast<const float4*>(
            Q + ((size_t)(b * N_ + qi) * H_ + h) * D_ + d0);
        float x[32];
        #pragma unroll
        for (int i = 0; i < 8; ++i) {
            float4 f = qp[i];
            x[4*i]   = f.x * QSCALE; x[4*i+1] = f.y * QSCALE;
            x[4*i+2] = f.z * QSCALE; x[4*i+3] = f.w * QSCALE;
        }
        uint32_t rb = (uint32_t)row * 128;
        #pragma unroll
        for (int j = 0; j < 8; ++j) {
            uint32_t h0, l0, h1, l1;
            split2(x[4*j], x[4*j+1], h0, l0);
            split2(x[4*j+2], x[4*j+3], h1, l1);
            uint32_t off = swz(rb + (uint32_t)(d0 + 4*j) * 2);
            *reinterpret_cast<uint2*>(sm + OFF_QH + off) = make_uint2(h0, h1);
            *reinterpret_cast<uint2*>(sm + OFF_QL + off) = make_uint2(l0, l1);
        }
    }

    // ---- K/V: thread owns (key = tid&63, d0 = (tid>>6)*32, 32 floats) ----
    const int key = tid & 63, kd0 = (tid >> 6) * 32;
    const float* kbase = K + ((size_t)(b * N_ + key) * H_ + h) * D_ + kd0;
    const float* vbase = V + ((size_t)(b * N_ + key) * H_ + h) * D_ + kd0;
    constexpr size_t TSTRIDE = (size_t)BK * H_ * D_;

    // loop-invariant swizzled store offsets (8 x uint2 slots per thread)
    uint32_t soff[8];
    #pragma unroll
    for (int j = 0; j < 8; ++j)
        soff[j] = swz((uint32_t)key * 128 + (uint32_t)(kd0 + 4*j) * 2);

    __align__(16) float kr[32], vr[32];
    ldg32(kr, kbase);
    ldg32(vr, vbase);
    stTile(sm, OFF_KH, OFF_KL, soff, kr);
    stTile(sm, OFF_VH, OFF_VL, soff, vr);
    __syncthreads();

    // ---- lane geometry for ldmatrix / fragments ----
    const int grp = lane >> 3, rr = lane & 7;
    const int rowsel = (grp & 1) * 8 + rr;   // row within 16-row tile pair
    const int colsel = (grp >> 1) * 8;       // 0 or 8 (b16 cols)
    const int g = lane >> 2, q = lane & 3;

    // ---- persistent Q fragments: warp wid owns rows wid*16..+15 ----
    uint32_t qh[4][4], ql[4][4];
    #pragma unroll
    for (int ks = 0; ks < 4; ++ks) {
        uint32_t off = swz((uint32_t)((wid * 16 + rowsel) << 7) +
                           (uint32_t)((ks * 16 + colsel) << 1));
        ldsm4(qh[ks], sb + OFF_QH + off);
        ldsm4(ql[ks], sb + OFF_QL + off);
    }

    float oC[8][4];
    #pragma unroll
    for (int f = 0; f < 8; ++f)
        #pragma unroll
        for (int i = 0; i < 4; ++i) oC[f][i] = 0.f;
    float l0 = 0.f, l1 = 0.f;

    // =========================== mainloop ===========================
    for (int t = 0; t < TILES; ++t) {
        const bool pre = (t + 1 < TILES);
        if (pre) ldg32(kr, kbase + (size_t)(t + 1) * TSTRIDE);

        // ---- S = Q Kt^T (3 compensated passes) ----
        float sC[8][4];
        #pragma unroll
        for (int f = 0; f < 8; ++f)
            #pragma unroll
            for (int i = 0; i < 4; ++i) sC[f][i] = 0.f;

        #pragma unroll
        for (int ks = 0; ks < 4; ++ks) {
            uint32_t kh[16], kl[16];
            #pragma unroll
            for (int fp = 0; fp < 4; ++fp) {
                uint32_t off = swz((uint32_t)((fp * 16 + rowsel) << 7) +
                                   (uint32_t)((ks * 16 + colsel) << 1));
                uint32_t r4[4];
                ldsm4(r4, sb + OFF_KH + off);
                kh[4*fp] = r4[0]; kh[4*fp+1] = r4[2]; kh[4*fp+2] = r4[1]; kh[4*fp+3] = r4[3];
                ldsm4(r4, sb + OFF_KL + off);
                kl[4*fp] = r4[0]; kl[4*fp+1] = r4[2]; kl[4*fp+2] = r4[1]; kl[4*fp+3] = r4[3];
            }
            #pragma unroll
            for (int f = 0; f < 8; ++f) mma16816(sC[f], qh[ks], &kh[2*f]);
            #pragma unroll
            for (int f = 0; f < 8; ++f) mma16816(sC[f], qh[ks], &kl[2*f]);
            #pragma unroll
            for (int f = 0; f < 8; ++f) mma16816(sC[f], ql[ks], &kh[2*f]);
        }

        // ---- softmax (base-2, no max: logits bounded) ----
        float p[8][4];
        #pragma unroll
        for (int f = 0; f < 8; ++f) {
            p[f][0] = ex2(sC[f][0]); p[f][1] = ex2(sC[f][1]);
            p[f][2] = ex2(sC[f][2]); p[f][3] = ex2(sC[f][3]);
            l0 += p[f][0] + p[f][1];
            l1 += p[f][2] + p[f][3];
        }
        // P accum frags -> A frags (in-register), bf16 hi/lo
        uint32_t ph[4][4], pl[4][4];
        #pragma unroll
        for (int kk = 0; kk < 4; ++kk) {
            int f0 = 2 * kk, f1 = f0 + 1;
            split2(p[f0][0], p[f0][1], ph[kk][0], pl[kk][0]);
            split2(p[f0][2], p[f0][3], ph[kk][1], pl[kk][1]);
            split2(p[f1][0], p[f1][1], ph[kk][2], pl[kk][2]);
            split2(p[f1][2], p[f1][3], ph[kk][3], pl[kk][3]);
        }

        if (pre) ldg32(vr, vbase + (size_t)(t + 1) * TSTRIDE);

        // ---- O += P V (3 compensated passes) ----
        #pragma unroll
        for (int ks = 0; ks < 4; ++ks) {
            uint32_t vh[16], vl[16];
            #pragma unroll
            for (int dp = 0; dp < 4; ++dp) {
                uint32_t off = swz((uint32_t)((ks * 16 + rowsel) << 7) +
                                   (uint32_t)((dp * 16 + colsel) << 1));
                uint32_t r4[4];
                ldsm4t(r4, sb + OFF_VH + off);
                vh[4*dp] = r4[0]; vh[4*dp+1] = r4[1]; vh[4*dp+2] = r4[2]; vh[4*dp+3] = r4[3];
                ldsm4t(r4, sb + OFF_VL + off);
                vl[4*dp] = r4[0]; vl[4*dp+1] = r4[1]; vl[4*dp+2] = r4[2]; vl[4*dp+3] = r4[3];
            }
            #pragma unroll
            for (int f = 0; f < 8; ++f) mma16816(oC[f], ph[ks], &vh[2*f]);
            #pragma unroll
            for (int f = 0; f < 8; ++f) mma16816(oC[f], pl[ks], &vh[2*f]);
            #pragma unroll
            for (int f = 0; f < 8; ++f) mma16816(oC[f], ph[ks], &vl[2*f]);
        }

        if (pre) {
            __syncthreads();   // all warps done reading tile t
            stTile(sm, OFF_KH, OFF_KL, soff, kr);
            stTile(sm, OFF_VH, OFF_VL, soff, vr);
            __syncthreads();
        }
    }

    // ---- row-sum reduce across the 4 lanes sharing a row ----
    l0 += __shfl_xor_sync(0xffffffffu, l0, 1);
    l0 += __shfl_xor_sync(0xffffffffu, l0, 2);
    l1 += __shfl_xor_sync(0xffffffffu, l1, 1);
    l1 += __shfl_xor_sync(0xffffffffu, l1, 2);

    __syncthreads();   // everyone done with smem tiles before staging overwrites

    // ---- normalize + stage O to smem ----
    {
        float inv0 = 1.f / l0, inv1 = 1.f / l1;
        float* stg = reinterpret_cast<float*>(sm + 1024);
        int r0 = wid * 16 + g, r1 = r0 + 8;
        #pragma unroll
        for (int f = 0; f < 8; ++f) {
            int col = 8 * f + 2 * q;
            stg[r0 * STG_LD + col]     = oC[f][0] * inv0;
            stg[r0 * STG_LD + col + 1] = oC[f][1] * inv0;
            stg[r1 * STG_LD + col]     = oC[f][2] * inv1;
            stg[r1 * STG_LD + col + 1] = oC[f][3] * inv1;
        }
    }
    __syncthreads();

    // ---- combine top - lambda*bottom, write out (32 rows x 64 cols) ----
    {
        const float lam = *reinterpret_cast<const float*>(sm);
        const float* stg = reinterpret_cast<const float*>(sm + 1024);
        #pragma unroll
        for (int it = 0; it < 4; ++it) {
            int slot = it * THREADS + tid;
            int r = slot >> 4, c4 = (slot & 15) << 2;
            float4 tp = *reinterpret_cast<const float4*>(stg + (size_t)r * STG_LD + c4);
            float4 bt = *reinterpret_cast<const float4*>(stg + (size_t)(r + BQ) * STG_LD + c4);
            float4 res;
            res.x = tp.x - lam * bt.x; res.y = tp.y - lam * bt.y;
            res.z = tp.z - lam * bt.z; res.w = tp.w - lam * bt.w;
            *reinterpret_cast<float4*>(
                out + ((size_t)((b * H_ + h) * NO_) + qi0 + r) * D_ + c4) = res;
        }
    }
}

}  // namespace

extern "C" void kernel_launch(void* const* d_in, const int* in_sizes, int n_in,
                              void* d_out, int out_size)
{
    (void)in_sizes; (void)n_in; (void)out_size;
    const float* q   = (const float*)d_in[0];
    const float* k   = (const float*)d_in[1];
    const float* v   = (const float*)d_in[2];
    const float* lq1 = (const float*)d_in[3];
    const float* lk1 = (const float*)d_in[4];
    const float* lq2 = (const float*)d_in[5];
    const float* lk2 = (const float*)d_in[6];
    float* out = (float*)d_out;

    cudaFuncSetAttribute(diff_attn_hmma,
                         cudaFuncAttributeMaxDynamicSharedMemorySize, SMEM_TOTAL);
    dim3 grid(NO_ / BQ, H_, B_);   // (32, 8, 2) = 512 CTAs
    diff_attn_hmma<<<grid, THREADS, SMEM_TOTAL>>>(q, k, v, lq1, lk1, lq2, lk2, out);
}

// round 13
// speedup vs baseline: 1.1331x; 1.1331x over previous
#include <cuda_runtime.h>
#include <cuda_bf16.h>
#include <cstdint>

#define LAMBDA_INIT_F 0.32802328f   // 0.8 - 0.6*exp(-0.3*0.8)

namespace {

constexpr int B_ = 2, N_ = 2048, H_ = 8, D_ = 64, NO_ = 1024;
constexpr int BQ = 64, BK = 64, TILES = N_ / BK;
constexpr int THREADS = 256;
constexpr float QSCALE = 0.125f * 1.4426950408889634f;  // 1/sqrt(64) * log2(e)

// pre-converted K/V in [b][h][n][d] bf16 (hi/lo error-split), 4MB each
constexpr size_t KVELEMS = (size_t)B_ * H_ * N_ * D_;   // 2M

// smem layout (bytes). Row stride 128B for all bf16 tiles (64 bf16/row).
// Q hi/lo single; K/V hi/lo double-buffered (cp.async).
constexpr int OFF_QH  = 1024;                 // 128 x 128B
constexpr int OFF_QL  = OFF_QH + 16384;
constexpr int OFF_KH0 = OFF_QL + 16384;       // 64 x 128B each below
constexpr int OFF_KL0 = OFF_KH0 + 8192;
constexpr int OFF_VH0 = OFF_KL0 + 8192;
constexpr int OFF_VL0 = OFF_VH0 + 8192;
constexpr int OFF_KH1 = OFF_VL0 + 8192;
constexpr int OFF_KL1 = OFF_KH1 + 8192;
constexpr int OFF_VH1 = OFF_KL1 + 8192;
constexpr int OFF_VL1 = OFF_VH1 + 8192;
constexpr int SMEM_TOTAL = OFF_VL1 + 8192;    // 99328 B -> 1 CTA/SM
constexpr int STG_LD = 68;                    // epilogue staging stride (floats)

__device__ __align__(16) __nv_bfloat16 g_kh[KVELEMS];
__device__ __align__(16) __nv_bfloat16 g_kl[KVELEMS];
__device__ __align__(16) __nv_bfloat16 g_vh[KVELEMS];
__device__ __align__(16) __nv_bfloat16 g_vl[KVELEMS];

__device__ __forceinline__ uint32_t s2u(const void* p) {
    uint32_t a;
    asm("{ .reg .u64 t; cvta.to.shared.u64 t, %1; cvt.u32.u64 %0, t; }" : "=r"(a) : "l"(p));
    return a;
}
__device__ __forceinline__ uint32_t swz(uint32_t x) { return x ^ ((x >> 3) & 0x70); }
__device__ __forceinline__ float ex2(float x) {
    float y; asm("ex2.approx.ftz.f32 %0, %1;" : "=f"(y) : "f"(x)); return y;
}
// bf16 hi/lo split of two floats, packed bf16x2 (first value in low half)
__device__ __forceinline__ void split2(float x0, float x1, uint32_t& hp, uint32_t& lp) {
    __nv_bfloat16 h0 = __float2bfloat16(x0), h1 = __float2bfloat16(x1);
    float l0 = x0 - __bfloat162float(h0), l1 = x1 - __bfloat162float(h1);
    hp = ((uint32_t)__bfloat16_as_ushort(h1) << 16) | (uint32_t)__bfloat16_as_ushort(h0);
    __nv_bfloat162 lb = __floats2bfloat162_rn(l0, l1);
    lp = *reinterpret_cast<uint32_t*>(&lb);
}

__device__ __forceinline__ void mma16816(float* c, const uint32_t* a, const uint32_t* b) {
    asm volatile(
        "mma.sync.aligned.m16n8k16.row.col.f32.bf16.bf16.f32 "
        "{%0,%1,%2,%3}, {%4,%5,%6,%7}, {%8,%9}, {%0,%1,%2,%3};"
        : "+f"(c[0]), "+f"(c[1]), "+f"(c[2]), "+f"(c[3])
        : "r"(a[0]), "r"(a[1]), "r"(a[2]), "r"(a[3]), "r"(b[0]), "r"(b[1]));
}
__device__ __forceinline__ void ldsm4(uint32_t* r, uint32_t addr) {
    asm volatile("ldmatrix.sync.aligned.m8n8.x4.shared.b16 {%0,%1,%2,%3}, [%4];"
                 : "=r"(r[0]), "=r"(r[1]), "=r"(r[2]), "=r"(r[3]) : "r"(addr));
}
__device__ __forceinline__ void ldsm4t(uint32_t* r, uint32_t addr) {
    asm volatile("ldmatrix.sync.aligned.m8n8.x4.trans.shared.b16 {%0,%1,%2,%3}, [%4];"
                 : "=r"(r[0]), "=r"(r[1]), "=r"(r[2]), "=r"(r[3]) : "r"(addr));
}
__device__ __forceinline__ void cp16(uint32_t dst, const void* src) {
    asm volatile("cp.async.ca.shared.global [%0], [%1], 16;" :: "r"(dst), "l"(src) : "memory");
}
__device__ __forceinline__ void cp_commit() {
    asm volatile("cp.async.commit_group;" ::: "memory");
}
__device__ __forceinline__ void cp_wait0() {
    asm volatile("cp.async.wait_group 0;" ::: "memory");
}

// ---------------- pre-kernel: K/V fp32 [b][n][h][d] -> bf16 hi/lo [b][h][n][d] ----------------
__global__ void __launch_bounds__(256)
conv_kv(const float* __restrict__ K, const float* __restrict__ V)
{
    int idx = blockIdx.x * 256 + threadIdx.x;     // 262144 total
    int dc = idx & 7;                             // 8-elem d chunk
    int n  = (idx >> 3) & (N_ - 1);
    int h  = (idx >> 14) & (H_ - 1);
    int b  = idx >> 17;
    size_t src = (((size_t)(b * N_ + n) * H_ + h) * D_) + dc * 8;
    size_t dst = (((size_t)(b * H_ + h) * N_ + n) * D_) + dc * 8;

    float4 k0 = *reinterpret_cast<const float4*>(K + src);
    float4 k1 = *reinterpret_cast<const float4*>(K + src + 4);
    float4 v0 = *reinterpret_cast<const float4*>(V + src);
    float4 v1 = *reinterpret_cast<const float4*>(V + src + 4);

    uint4 kh, kl, vh, vl;
    split2(k0.x, k0.y, kh.x, kl.x); split2(k0.z, k0.w, kh.y, kl.y);
    split2(k1.x, k1.y, kh.z, kl.z); split2(k1.z, k1.w, kh.w, kl.w);
    split2(v0.x, v0.y, vh.x, vl.x); split2(v0.z, v0.w, vh.y, vl.y);
    split2(v1.x, v1.y, vh.z, vl.z); split2(v1.z, v1.w, vh.w, vl.w);

    *reinterpret_cast<uint4*>(g_kh + dst) = kh;
    *reinterpret_cast<uint4*>(g_kl + dst) = kl;
    *reinterpret_cast<uint4*>(g_vh + dst) = vh;
    *reinterpret_cast<uint4*>(g_vl + dst) = vl;
}

// ---------------- main kernel ----------------
__global__ void __launch_bounds__(THREADS, 1)
diff_attn_hmma(const float* __restrict__ Q,
               const float* __restrict__ lq1, const float* __restrict__ lk1,
               const float* __restrict__ lq2, const float* __restrict__ lk2,
               float* __restrict__ out)
{
    extern __shared__ __align__(128) char sm[];
    const uint32_t sb = s2u(sm);
    const int tid = threadIdx.x;
    const int wid = tid >> 5, lane = tid & 31;
    const int qb = blockIdx.x, h = blockIdx.y, b = blockIdx.z;
    const int qi0 = qb * BQ;

    // ---- lambda (warp 2) ----
    if (wid == 2) {
        float p1 = lq1[lane] * lk1[lane] + lq1[lane + 32] * lk1[lane + 32];
        float p2 = lq2[lane] * lk2[lane] + lq2[lane + 32] * lk2[lane + 32];
        #pragma unroll
        for (int o = 16; o; o >>= 1) {
            p1 += __shfl_xor_sync(0xffffffffu, p1, o);
            p2 += __shfl_xor_sync(0xffffffffu, p2, o);
        }
        if (lane == 0)
            *reinterpret_cast<float*>(sm) = __expf(p1) - __expf(p2) + LAMBDA_INIT_F;
    }

    // ---- cp.async geometry: thread owns (key = tid&63, 16B segs {2sc, 2sc+1}) ----
    const int key = tid & 63, sc = tid >> 6;          // sc in [0,4)
    uint32_t soff[2];
    #pragma unroll
    for (int j = 0; j < 2; ++j)
        soff[j] = swz((uint32_t)key * 128 + (uint32_t)(sc * 32 + j * 16));
    const size_t kvbase = ((size_t)(b * H_ + h) * N_ + key) * D_ + sc * 16;

    // issue tile t into buffer sel
    auto issue_tile = [&](int t, int sel) {
        size_t g = kvbase + (size_t)t * BK * D_;
        const uint32_t kh = sel ? OFF_KH1 : OFF_KH0, kl = sel ? OFF_KL1 : OFF_KL0;
        const uint32_t vh = sel ? OFF_VH1 : OFF_VH0, vl = sel ? OFF_VL1 : OFF_VL0;
        #pragma unroll
        for (int j = 0; j < 2; ++j) {
            size_t gj = g + j * 8;
            cp16(sb + kh + soff[j], g_kh + gj);
            cp16(sb + kl + soff[j], g_kl + gj);
            cp16(sb + vh + soff[j], g_vh + gj);
            cp16(sb + vl + soff[j], g_vl + gj);
        }
        cp_commit();
    };

    issue_tile(0, 0);   // prologue: tile 0 in flight while we stage Q

    // ---- stage Q (128 rows: 64 top | 64 bottom), scaled, bf16 hi/lo ----
    {
        int row = tid & 127, d0 = (tid >> 7) * 32;
        int qi = qi0 + ((row < BQ) ? row : row - BQ + NO_);
        const float4* qp = reinterpret_cast<const float4*>(
            Q + ((size_t)(b * N_ + qi) * H_ + h) * D_ + d0);
        float x[32];
        #pragma unroll
        for (int i = 0; i < 8; ++i) {
            float4 f = qp[i];
            x[4*i]   = f.x * QSCALE; x[4*i+1] = f.y * QSCALE;
            x[4*i+2] = f.z * QSCALE; x[4*i+3] = f.w * QSCALE;
        }
        uint32_t rb = (uint32_t)row * 128;
        #pragma unroll
        for (int j = 0; j < 8; ++j) {
            uint32_t h0, l0, h1, l1;
            split2(x[4*j], x[4*j+1], h0, l0);
            split2(x[4*j+2], x[4*j+3], h1, l1);
            uint32_t off = swz(rb + (uint32_t)(d0 + 4*j) * 2);
            *reinterpret_cast<uint2*>(sm + OFF_QH + off) = make_uint2(h0, h1);
            *reinterpret_cast<uint2*>(sm + OFF_QL + off) = make_uint2(l0, l1);
        }
    }
    cp_wait0();
    __syncthreads();

    // ---- lane geometry for ldmatrix / fragments ----
    const int grp = lane >> 3, rr = lane & 7;
    const int rowsel = (grp & 1) * 8 + rr;   // row within 16-row tile pair
    const int colsel = (grp >> 1) * 8;       // 0 or 8 (b16 cols)
    const int g = lane >> 2, q = lane & 3;

    // ---- persistent Q fragments: warp wid owns rows wid*16..+15 ----
    uint32_t qh[4][4], ql[4][4];
    #pragma unroll
    for (int ks = 0; ks < 4; ++ks) {
        uint32_t off = swz((uint32_t)((wid * 16 + rowsel) << 7) +
                           (uint32_t)((ks * 16 + colsel) << 1));
        ldsm4(qh[ks], sb + OFF_QH + off);
        ldsm4(ql[ks], sb + OFF_QL + off);
    }

    float oC[8][4];
    #pragma unroll
    for (int f = 0; f < 8; ++f)
        #pragma unroll
        for (int i = 0; i < 4; ++i) oC[f][i] = 0.f;
    float l0 = 0.f, l1 = 0.f;

    // =========================== mainloop ===========================
    for (int t = 0; t < TILES; ++t) {
        const bool pre = (t + 1 < TILES);
        if (pre) issue_tile(t + 1, (t + 1) & 1);   // async, other buffer

        const uint32_t cKH = (t & 1) ? OFF_KH1 : OFF_KH0, cKL = (t & 1) ? OFF_KL1 : OFF_KL0;
        const uint32_t cVH = (t & 1) ? OFF_VH1 : OFF_VH0, cVL = (t & 1) ? OFF_VL1 : OFF_VL0;

        // ---- S = Q Kt^T (3 compensated passes, pass-major) ----
        float sC[8][4];
        #pragma unroll
        for (int f = 0; f < 8; ++f)
            #pragma unroll
            for (int i = 0; i < 4; ++i) sC[f][i] = 0.f;

        #pragma unroll
        for (int ks = 0; ks < 4; ++ks) {
            uint32_t kh[16], kl[16];
            #pragma unroll
            for (int fp = 0; fp < 4; ++fp) {
                uint32_t off = swz((uint32_t)((fp * 16 + rowsel) << 7) +
                                   (uint32_t)((ks * 16 + colsel) << 1));
                uint32_t r4[4];
                ldsm4(r4, sb + cKH + off);
                kh[4*fp] = r4[0]; kh[4*fp+1] = r4[2]; kh[4*fp+2] = r4[1]; kh[4*fp+3] = r4[3];
                ldsm4(r4, sb + cKL + off);
                kl[4*fp] = r4[0]; kl[4*fp+1] = r4[2]; kl[4*fp+2] = r4[1]; kl[4*fp+3] = r4[3];
            }
            #pragma unroll
            for (int f = 0; f < 8; ++f) mma16816(sC[f], qh[ks], &kh[2*f]);
            #pragma unroll
            for (int f = 0; f < 8; ++f) mma16816(sC[f], qh[ks], &kl[2*f]);
            #pragma unroll
            for (int f = 0; f < 8; ++f) mma16816(sC[f], ql[ks], &kh[2*f]);
        }

        // ---- softmax (base-2, no max: logits bounded) ----
        float p[8][4];
        #pragma unroll
        for (int f = 0; f < 8; ++f) {
            p[f][0] = ex2(sC[f][0]); p[f][1] = ex2(sC[f][1]);
            p[f][2] = ex2(sC[f][2]); p[f][3] = ex2(sC[f][3]);
            l0 += p[f][0] + p[f][1];
            l1 += p[f][2] + p[f][3];
        }
        // P accum frags -> A frags (in-register), bf16 hi/lo
        uint32_t ph[4][4], pl[4][4];
        #pragma unroll
        for (int kk = 0; kk < 4; ++kk) {
            int f0 = 2 * kk, f1 = f0 + 1;
            split2(p[f0][0], p[f0][1], ph[kk][0], pl[kk][0]);
            split2(p[f0][2], p[f0][3], ph[kk][1], pl[kk][1]);
            split2(p[f1][0], p[f1][1], ph[kk][2], pl[kk][2]);
            split2(p[f1][2], p[f1][3], ph[kk][3], pl[kk][3]);
        }

        // ---- O += P V (3 compensated passes, pass-major) ----
        #pragma unroll
        for (int ks = 0; ks < 4; ++ks) {
            uint32_t vh[16], vl[16];
            #pragma unroll
            for (int dp = 0; dp < 4; ++dp) {
                uint32_t off = swz((uint32_t)((ks * 16 + rowsel) << 7) +
                                   (uint32_t)((dp * 16 + colsel) << 1));
                uint32_t r4[4];
                ldsm4t(r4, sb + cVH + off);
                vh[4*dp] = r4[0]; vh[4*dp+1] = r4[1]; vh[4*dp+2] = r4[2]; vh[4*dp+3] = r4[3];
                ldsm4t(r4, sb + cVL + off);
                vl[4*dp] = r4[0]; vl[4*dp+1] = r4[1]; vl[4*dp+2] = r4[2]; vl[4*dp+3] = r4[3];
            }
            #pragma unroll
            for (int f = 0; f < 8; ++f) mma16816(oC[f], ph[ks], &vh[2*f]);
            #pragma unroll
            for (int f = 0; f < 8; ++f) mma16816(oC[f], pl[ks], &vh[2*f]);
            #pragma unroll
            for (int f = 0; f < 8; ++f) mma16816(oC[f], ph[ks], &vl[2*f]);
        }

        if (pre) {
            cp_wait0();        // next tile landed
            __syncthreads();   // all warps done reading current buffer; swap safe
        }
    }

    // ---- row-sum reduce across the 4 lanes sharing a row ----
    l0 += __shfl_xor_sync(0xffffffffu, l0, 1);
    l0 += __shfl_xor_sync(0xffffffffu, l0, 2);
    l1 += __shfl_xor_sync(0xffffffffu, l1, 1);
    l1 += __shfl_xor_sync(0xffffffffu, l1, 2);

    __syncthreads();   // everyone done with smem tiles before staging overwrites

    // ---- normalize + stage O to smem ----
    {
        float inv0 = 1.f / l0, inv1 = 1.f / l1;
        float* stg = reinterpret_cast<float*>(sm + 1024);
        int r0 = wid * 16 + g, r1 = r0 + 8;
        #pragma unroll
        for (int f = 0; f < 8; ++f) {
            int col = 8 * f + 2 * q;
            stg[r0 * STG_LD + col]     = oC[f][0] * inv0;
            stg[r0 * STG_LD + col + 1] = oC[f][1] * inv0;
            stg[r1 * STG_LD + col]     = oC[f][2] * inv1;
            stg[r1 * STG_LD + col + 1] = oC[f][3] * inv1;
        }
    }
    __syncthreads();

    // ---- combine top - lambda*bottom, write out ----
    {
        const float lam = *reinterpret_cast<const float*>(sm);
        const float* stg = reinterpret_cast<const float*>(sm + 1024);
        #pragma unroll
        for (int it = 0; it < 4; ++it) {
            int slot = it * THREADS + tid;
            int r = slot >> 4, c4 = (slot & 15) << 2;
            float4 tp = *reinterpret_cast<const float4*>(stg + (size_t)r * STG_LD + c4);
            float4 bt = *reinterpret_cast<const float4*>(stg + (size_t)(r + BQ) * STG_LD + c4);
            float4 res;
            res.x = tp.x - lam * bt.x; res.y = tp.y - lam * bt.y;
            res.z = tp.z - lam * bt.z; res.w = tp.w - lam * bt.w;
            *reinterpret_cast<float4*>(
                out + ((size_t)((b * H_ + h) * NO_) + qi0 + r) * D_ + c4) = res;
        }
    }
}

}  // namespace

extern "C" void kernel_launch(void* const* d_in, const int* in_sizes, int n_in,
                              void* d_out, int out_size)
{
    (void)in_sizes; (void)n_in; (void)out_size;
    const float* q   = (const float*)d_in[0];
    const float* k   = (const float*)d_in[1];
    const float* v   = (const float*)d_in[2];
    const float* lq1 = (const float*)d_in[3];
    const float* lk1 = (const float*)d_in[4];
    const float* lq2 = (const float*)d_in[5];
    const float* lk2 = (const float*)d_in[6];
    float* out = (float*)d_out;

    conv_kv<<<1024, 256>>>(k, v);   // K/V -> bf16 hi/lo, [b][h][n][d]

    cudaFuncSetAttribute(diff_attn_hmma,
                         cudaFuncAttributeMaxDynamicSharedMemorySize, SMEM_TOTAL);
    dim3 grid(NO_ / BQ, H_, B_);    // (16, 8, 2) = 256 CTAs
    diff_attn_hmma<<<grid, THREADS, SMEM_TOTAL>>>(q, lq1, lk1, lq2, lk2, out);
}

// round 14
// speedup vs baseline: 1.3269x; 1.1710x over previous
#include <cuda_runtime.h>
#include <cuda_bf16.h>
#include <cstdint>

#define LAMBDA_INIT_F 0.32802328f   // 0.8 - 0.6*exp(-0.3*0.8)

namespace {

constexpr int B_ = 2, N_ = 2048, H_ = 8, D_ = 64, NO_ = 1024;
constexpr int BQ = 64, BK = 64, TILES = N_ / BK;
constexpr int THREADS = 256;
constexpr float QSCALE = 0.125f * 1.4426950408889634f;  // 1/sqrt(64) * log2(e)

// pre-converted K/V in [b][h][n][d] bf16 (hi/lo error-split)
constexpr size_t KVELEMS = (size_t)B_ * H_ * N_ * D_;   // 2M

// smem layout (bytes). Row stride 128B for all bf16 tiles (64 bf16/row).
constexpr int OFF_QH = 1024;              // 128 x 128B
constexpr int OFF_QL = OFF_QH + 16384;
constexpr int OFF_KH = OFF_QL + 16384;    // 64 x 128B
constexpr int OFF_KL = OFF_KH + 8192;
constexpr int OFF_VH = OFF_KL + 8192;
constexpr int OFF_VL = OFF_VH + 8192;
constexpr int SMEM_TOTAL = OFF_VL + 8192; // 66560 B
constexpr int STG_LD = 68;                // epilogue staging stride (floats)

__device__ __align__(16) __nv_bfloat16 g_kh[KVELEMS];
__device__ __align__(16) __nv_bfloat16 g_kl[KVELEMS];
__device__ __align__(16) __nv_bfloat16 g_vh[KVELEMS];
__device__ __align__(16) __nv_bfloat16 g_vl[KVELEMS];

__device__ __forceinline__ uint32_t s2u(const void* p) {
    uint32_t a;
    asm("{ .reg .u64 t; cvta.to.shared.u64 t, %1; cvt.u32.u64 %0, t; }" : "=r"(a) : "l"(p));
    return a;
}
__device__ __forceinline__ uint32_t swz(uint32_t x) { return x ^ ((x >> 3) & 0x70); }
__device__ __forceinline__ float ex2(float x) {
    float y; asm("ex2.approx.ftz.f32 %0, %1;" : "=f"(y) : "f"(x)); return y;
}
// bf16 hi/lo split of two floats, packed bf16x2 (first value in low half)
__device__ __forceinline__ void split2(float x0, float x1, uint32_t& hp, uint32_t& lp) {
    __nv_bfloat16 h0 = __float2bfloat16(x0), h1 = __float2bfloat16(x1);
    float l0 = x0 - __bfloat162float(h0), l1 = x1 - __bfloat162float(h1);
    hp = ((uint32_t)__bfloat16_as_ushort(h1) << 16) | (uint32_t)__bfloat16_as_ushort(h0);
    __nv_bfloat162 lb = __floats2bfloat162_rn(l0, l1);
    lp = *reinterpret_cast<uint32_t*>(&lb);
}

__device__ __forceinline__ void mma16816(float* c, const uint32_t* a, const uint32_t* b) {
    asm volatile(
        "mma.sync.aligned.m16n8k16.row.col.f32.bf16.bf16.f32 "
        "{%0,%1,%2,%3}, {%4,%5,%6,%7}, {%8,%9}, {%0,%1,%2,%3};"
        : "+f"(c[0]), "+f"(c[1]), "+f"(c[2]), "+f"(c[3])
        : "r"(a[0]), "r"(a[1]), "r"(a[2]), "r"(a[3]), "r"(b[0]), "r"(b[1]));
}
__device__ __forceinline__ void ldsm4(uint32_t* r, uint32_t addr) {
    asm volatile("ldmatrix.sync.aligned.m8n8.x4.shared.b16 {%0,%1,%2,%3}, [%4];"
                 : "=r"(r[0]), "=r"(r[1]), "=r"(r[2]), "=r"(r[3]) : "r"(addr));
}
__device__ __forceinline__ void ldsm4t(uint32_t* r, uint32_t addr) {
    asm volatile("ldmatrix.sync.aligned.m8n8.x4.trans.shared.b16 {%0,%1,%2,%3}, [%4];"
                 : "=r"(r[0]), "=r"(r[1]), "=r"(r[2]), "=r"(r[3]) : "r"(addr));
}

// ---------------- pre-kernel: K/V fp32 [b][n][h][d] -> bf16 hi/lo [b][h][n][d] ----------------
__global__ void __launch_bounds__(256)
conv_kv(const float* __restrict__ K, const float* __restrict__ V)
{
    int idx = blockIdx.x * 256 + threadIdx.x;     // 262144 total
    int dc = idx & 7;                             // 8-elem d chunk
    int n  = (idx >> 3) & (N_ - 1);
    int h  = (idx >> 14) & (H_ - 1);
    int b  = idx >> 17;
    size_t src = (((size_t)(b * N_ + n) * H_ + h) * D_) + dc * 8;
    size_t dst = (((size_t)(b * H_ + h) * N_ + n) * D_) + dc * 8;

    float4 k0 = *reinterpret_cast<const float4*>(K + src);
    float4 k1 = *reinterpret_cast<const float4*>(K + src + 4);
    float4 v0 = *reinterpret_cast<const float4*>(V + src);
    float4 v1 = *reinterpret_cast<const float4*>(V + src + 4);

    uint4 kh, kl, vh, vl;
    split2(k0.x, k0.y, kh.x, kl.x); split2(k0.z, k0.w, kh.y, kl.y);
    split2(k1.x, k1.y, kh.z, kl.z); split2(k1.z, k1.w, kh.w, kl.w);
    split2(v0.x, v0.y, vh.x, vl.x); split2(v0.z, v0.w, vh.y, vl.y);
    split2(v1.x, v1.y, vh.z, vl.z); split2(v1.z, v1.w, vh.w, vl.w);

    *reinterpret_cast<uint4*>(g_kh + dst) = kh;
    *reinterpret_cast<uint4*>(g_kl + dst) = kl;
    *reinterpret_cast<uint4*>(g_vh + dst) = vh;
    *reinterpret_cast<uint4*>(g_vl + dst) = vl;
}

// ---------------- main kernel (round-11 skeleton, bf16 gmem staging) ----------------
__global__ void __launch_bounds__(THREADS, 1)
diff_attn_hmma(const float* __restrict__ Q,
               const float* __restrict__ lq1, const float* __restrict__ lk1,
               const float* __restrict__ lq2, const float* __restrict__ lk2,
               float* __restrict__ out)
{
    extern __shared__ __align__(128) char sm[];
    const uint32_t sb = s2u(sm);
    const int tid = threadIdx.x;
    const int wid = tid >> 5, lane = tid & 31;
    const int qb = blockIdx.x, h = blockIdx.y, b = blockIdx.z;
    const int qi0 = qb * BQ;

    // ---- lambda (warp 2) ----
    if (wid == 2) {
        float p1 = lq1[lane] * lk1[lane] + lq1[lane + 32] * lk1[lane + 32];
        float p2 = lq2[lane] * lk2[lane] + lq2[lane + 32] * lk2[lane + 32];
        #pragma unroll
        for (int o = 16; o; o >>= 1) {
            p1 += __shfl_xor_sync(0xffffffffu, p1, o);
            p2 += __shfl_xor_sync(0xffffffffu, p2, o);
        }
        if (lane == 0)
            *reinterpret_cast<float*>(sm) = __expf(p1) - __expf(p2) + LAMBDA_INIT_F;
    }

    // ---- stage Q (128 rows: 64 top | 64 bottom), scaled, bf16 hi/lo ----
    {
        int row = tid & 127, d0 = (tid >> 7) * 32;
        int qi = qi0 + ((row < BQ) ? row : row - BQ + NO_);
        const float4* qp = reinterpret_cast<const float4*>(
            Q + ((size_t)(b * N_ + qi) * H_ + h) * D_ + d0);
        float x[32];
        #pragma unroll
        for (int i = 0; i < 8; ++i) {
            float4 f = qp[i];
            x[4*i]   = f.x * QSCALE; x[4*i+1] = f.y * QSCALE;
            x[4*i+2] = f.z * QSCALE; x[4*i+3] = f.w * QSCALE;
        }
        uint32_t rb = (uint32_t)row * 128;
        #pragma unroll
        for (int j = 0; j < 8; ++j) {
            uint32_t h0, l0, h1, l1;
            split2(x[4*j], x[4*j+1], h0, l0);
            split2(x[4*j+2], x[4*j+3], h1, l1);
            uint32_t off = swz(rb + (uint32_t)(d0 + 4*j) * 2);
            *reinterpret_cast<uint2*>(sm + OFF_QH + off) = make_uint2(h0, h1);
            *reinterpret_cast<uint2*>(sm + OFF_QL + off) = make_uint2(l0, l1);
        }
    }

    // ---- K/V staging: thread owns (key = tid&63, d = kd0..kd0+15) ----
    const int key = tid & 63, kd0 = (tid >> 6) * 16;
    const size_t kvbase = ((size_t)(b * H_ + h) * N_ + key) * D_ + kd0;
    constexpr size_t TSTRIDE = (size_t)BK * D_;

    // swizzled 16B store slots (2 per matrix per thread)
    uint32_t soff2[2];
    #pragma unroll
    for (int j = 0; j < 2; ++j)
        soff2[j] = swz((uint32_t)key * 128 + (uint32_t)(kd0 * 2 + j * 16));

    uint4 skh[2], skl[2], svh[2], svl[2];
    #pragma unroll
    for (int j = 0; j < 2; ++j) {
        skh[j] = *reinterpret_cast<const uint4*>(g_kh + kvbase + j * 8);
        skl[j] = *reinterpret_cast<const uint4*>(g_kl + kvbase + j * 8);
        svh[j] = *reinterpret_cast<const uint4*>(g_vh + kvbase + j * 8);
        svl[j] = *reinterpret_cast<const uint4*>(g_vl + kvbase + j * 8);
    }
    #pragma unroll
    for (int j = 0; j < 2; ++j) {
        *reinterpret_cast<uint4*>(sm + OFF_KH + soff2[j]) = skh[j];
        *reinterpret_cast<uint4*>(sm + OFF_KL + soff2[j]) = skl[j];
        *reinterpret_cast<uint4*>(sm + OFF_VH + soff2[j]) = svh[j];
        *reinterpret_cast<uint4*>(sm + OFF_VL + soff2[j]) = svl[j];
    }
    __syncthreads();

    // ---- lane geometry for ldmatrix / fragments ----
    const int grp = lane >> 3, rr = lane & 7;
    const int rowsel = (grp & 1) * 8 + rr;   // row within 16-row tile pair
    const int colsel = (grp >> 1) * 8;       // 0 or 8 (b16 cols)
    const int g = lane >> 2, q = lane & 3;

    // ---- persistent Q fragments: warp wid owns rows wid*16..+15 ----
    uint32_t qh[4][4], ql[4][4];
    #pragma unroll
    for (int ks = 0; ks < 4; ++ks) {
        uint32_t off = swz((uint32_t)((wid * 16 + rowsel) << 7) +
                           (uint32_t)((ks * 16 + colsel) << 1));
        ldsm4(qh[ks], sb + OFF_QH + off);
        ldsm4(ql[ks], sb + OFF_QL + off);
    }

    float oC[8][4];
    #pragma unroll
    for (int f = 0; f < 8; ++f)
        #pragma unroll
        for (int i = 0; i < 4; ++i) oC[f][i] = 0.f;
    float l0 = 0.f, l1 = 0.f;

    // =========================== mainloop ===========================
    for (int t = 0; t < TILES; ++t) {
        const bool pre = (t + 1 < TILES);
        if (pre) {
            size_t gk = kvbase + (size_t)(t + 1) * TSTRIDE;
            #pragma unroll
            for (int j = 0; j < 2; ++j) {
                skh[j] = *reinterpret_cast<const uint4*>(g_kh + gk + j * 8);
                skl[j] = *reinterpret_cast<const uint4*>(g_kl + gk + j * 8);
            }
        }

        // ---- S = Q Kt^T (3 compensated passes, pass-major) ----
        float sC[8][4];
        #pragma unroll
        for (int f = 0; f < 8; ++f)
            #pragma unroll
            for (int i = 0; i < 4; ++i) sC[f][i] = 0.f;

        #pragma unroll
        for (int ks = 0; ks < 4; ++ks) {
            uint32_t kh[16], kl[16];
            #pragma unroll
            for (int fp = 0; fp < 4; ++fp) {
                uint32_t off = swz((uint32_t)((fp * 16 + rowsel) << 7) +
                                   (uint32_t)((ks * 16 + colsel) << 1));
                uint32_t r4[4];
                ldsm4(r4, sb + OFF_KH + off);
                kh[4*fp] = r4[0]; kh[4*fp+1] = r4[2]; kh[4*fp+2] = r4[1]; kh[4*fp+3] = r4[3];
                ldsm4(r4, sb + OFF_KL + off);
                kl[4*fp] = r4[0]; kl[4*fp+1] = r4[2]; kl[4*fp+2] = r4[1]; kl[4*fp+3] = r4[3];
            }
            #pragma unroll
            for (int f = 0; f < 8; ++f) mma16816(sC[f], qh[ks], &kh[2*f]);
            #pragma unroll
            for (int f = 0; f < 8; ++f) mma16816(sC[f], qh[ks], &kl[2*f]);
            #pragma unroll
            for (int f = 0; f < 8; ++f) mma16816(sC[f], ql[ks], &kh[2*f]);
        }

        // ---- softmax (base-2, no max: logits bounded) ----
        float p[8][4];
        #pragma unroll
        for (int f = 0; f < 8; ++f) {
            p[f][0] = ex2(sC[f][0]); p[f][1] = ex2(sC[f][1]);
            p[f][2] = ex2(sC[f][2]); p[f][3] = ex2(sC[f][3]);
            l0 += p[f][0] + p[f][1];
            l1 += p[f][2] + p[f][3];
        }
        // P accum frags -> A frags (in-register), bf16 hi/lo
        uint32_t ph[4][4], pl[4][4];
        #pragma unroll
        for (int kk = 0; kk < 4; ++kk) {
            int f0 = 2 * kk, f1 = f0 + 1;
            split2(p[f0][0], p[f0][1], ph[kk][0], pl[kk][0]);
            split2(p[f0][2], p[f0][3], ph[kk][1], pl[kk][1]);
            split2(p[f1][0], p[f1][1], ph[kk][2], pl[kk][2]);
            split2(p[f1][2], p[f1][3], ph[kk][3], pl[kk][3]);
        }

        if (pre) {
            size_t gv = kvbase + (size_t)(t + 1) * TSTRIDE;
            #pragma unroll
            for (int j = 0; j < 2; ++j) {
                svh[j] = *reinterpret_cast<const uint4*>(g_vh + gv + j * 8);
                svl[j] = *reinterpret_cast<const uint4*>(g_vl + gv + j * 8);
            }
        }

        // ---- O += P V (3 compensated passes, pass-major) ----
        #pragma unroll
        for (int ks = 0; ks < 4; ++ks) {
            uint32_t vh[16], vl[16];
            #pragma unroll
            for (int dp = 0; dp < 4; ++dp) {
                uint32_t off = swz((uint32_t)((ks * 16 + rowsel) << 7) +
                                   (uint32_t)((dp * 16 + colsel) << 1));
                uint32_t r4[4];
                ldsm4t(r4, sb + OFF_VH + off);
                vh[4*dp] = r4[0]; vh[4*dp+1] = r4[1]; vh[4*dp+2] = r4[2]; vh[4*dp+3] = r4[3];
                ldsm4t(r4, sb + OFF_VL + off);
                vl[4*dp] = r4[0]; vl[4*dp+1] = r4[1]; vl[4*dp+2] = r4[2]; vl[4*dp+3] = r4[3];
            }
            #pragma unroll
            for (int f = 0; f < 8; ++f) mma16816(oC[f], ph[ks], &vh[2*f]);
            #pragma unroll
            for (int f = 0; f < 8; ++f) mma16816(oC[f], pl[ks], &vh[2*f]);
            #pragma unroll
            for (int f = 0; f < 8; ++f) mma16816(oC[f], ph[ks], &vl[2*f]);
        }

        if (pre) {
            __syncthreads();   // all warps done reading tile t
            // tiny store window: 8 x STS.128, no conversion
            #pragma unroll
            for (int j = 0; j < 2; ++j) {
                *reinterpret_cast<uint4*>(sm + OFF_KH + soff2[j]) = skh[j];
                *reinterpret_cast<uint4*>(sm + OFF_KL + soff2[j]) = skl[j];
                *reinterpret_cast<uint4*>(sm + OFF_VH + soff2[j]) = svh[j];
                *reinterpret_cast<uint4*>(sm + OFF_VL + soff2[j]) = svl[j];
            }
            __syncthreads();
        }
    }

    // ---- row-sum reduce across the 4 lanes sharing a row ----
    l0 += __shfl_xor_sync(0xffffffffu, l0, 1);
    l0 += __shfl_xor_sync(0xffffffffu, l0, 2);
    l1 += __shfl_xor_sync(0xffffffffu, l1, 1);
    l1 += __shfl_xor_sync(0xffffffffu, l1, 2);

    __syncthreads();   // everyone done with smem tiles before staging overwrites

    // ---- normalize + stage O to smem ----
    {
        float inv0 = 1.f / l0, inv1 = 1.f / l1;
        float* stg = reinterpret_cast<float*>(sm + 1024);
        int r0 = wid * 16 + g, r1 = r0 + 8;
        #pragma unroll
        for (int f = 0; f < 8; ++f) {
            int col = 8 * f + 2 * q;
            stg[r0 * STG_LD + col]     = oC[f][0] * inv0;
            stg[r0 * STG_LD + col + 1] = oC[f][1] * inv0;
            stg[r1 * STG_LD + col]     = oC[f][2] * inv1;
            stg[r1 * STG_LD + col + 1] = oC[f][3] * inv1;
        }
    }
    __syncthreads();

    // ---- combine top - lambda*bottom, write out ----
    {
        const float lam = *reinterpret_cast<const float*>(sm);
        const float* stg = reinterpret_cast<const float*>(sm + 1024);
        #pragma unroll
        for (int it = 0; it < 4; ++it) {
            int slot = it * THREADS + tid;
            int r = slot >> 4, c4 = (slot & 15) << 2;
            float4 tp = *reinterpret_cast<const float4*>(stg + (size_t)r * STG_LD + c4);
            float4 bt = *reinterpret_cast<const float4*>(stg + (size_t)(r + BQ) * STG_LD + c4);
            float4 res;
            res.x = tp.x - lam * bt.x; res.y = tp.y - lam * bt.y;
            res.z = tp.z - lam * bt.z; res.w = tp.w - lam * bt.w;
            *reinterpret_cast<float4*>(
                out + ((size_t)((b * H_ + h) * NO_) + qi0 + r) * D_ + c4) = res;
        }
    }
}

}  // namespace

extern "C" void kernel_launch(void* const* d_in, const int* in_sizes, int n_in,
                              void* d_out, int out_size)
{
    (void)in_sizes; (void)n_in; (void)out_size;
    const float* q   = (const float*)d_in[0];
    const float* k   = (const float*)d_in[1];
    const float* v   = (const float*)d_in[2];
    const float* lq1 = (const float*)d_in[3];
    const float* lk1 = (const float*)d_in[4];
    const float* lq2 = (const float*)d_in[5];
    const float* lk2 = (const float*)d_in[6];
    float* out = (float*)d_out;

    conv_kv<<<1024, 256>>>(k, v);   // K/V -> bf16 hi/lo, [b][h][n][d]

    cudaFuncSetAttribute(diff_attn_hmma,
                         cudaFuncAttributeMaxDynamicSharedMemorySize, SMEM_TOTAL);
    dim3 grid(NO_ / BQ, H_, B_);    // (16, 8, 2) = 256 CTAs
    diff_attn_hmma<<<grid, THREADS, SMEM_TOTAL>>>(q, lq1, lk1, lq2, lk2, out);
}

// round 17
// speedup vs baseline: 1.6750x; 1.2624x over previous
#include <cuda_runtime.h>
#include <cuda_bf16.h>
#include <cuda_fp16.h>
#include <cstdint>

#define LAMBDA_INIT_F 0.32802328f   // 0.8 - 0.6*exp(-0.3*0.8)

namespace {

constexpr int B_ = 2, N_ = 2048, H_ = 8, D_ = 64, NO_ = 1024;
constexpr int BQ = 64, BK = 64, TILES = N_ / BK;
constexpr int THREADS = 256;
constexpr float QSCALE = 0.125f * 1.4426950408889634f;  // 1/sqrt(64) * log2(e)

constexpr size_t KVELEMS = (size_t)B_ * H_ * N_ * D_;   // 2M

// smem layout (bytes). Row stride 128B for all b16 tiles (64 elems/row).
constexpr int OFF_QH = 1024;              // 128 x 128B
constexpr int OFF_QL = OFF_QH + 16384;
constexpr int OFF_KH = OFF_QL + 16384;    // 64 x 128B
constexpr int OFF_KL = OFF_KH + 8192;
constexpr int OFF_VF = OFF_KL + 8192;     // 64 x 128B (fp16 V, single)
constexpr int SMEM_TOTAL = OFF_VF + 8192; // 58368 B
constexpr int STG_LD = 68;                // epilogue staging stride (floats)

__device__ __align__(16) __nv_bfloat16 g_kh[KVELEMS];
__device__ __align__(16) __nv_bfloat16 g_kl[KVELEMS];
__device__ __align__(16) __half        g_vf[KVELEMS];

__device__ __forceinline__ uint32_t s2u(const void* p) {
    uint32_t a;
    asm("{ .reg .u64 t; cvta.to.shared.u64 t, %1; cvt.u32.u64 %0, t; }" : "=r"(a) : "l"(p));
    return a;
}
__device__ __forceinline__ uint32_t swz(uint32_t x) { return x ^ ((x >> 3) & 0x70); }
__device__ __forceinline__ float ex2(float x) {
    float y; asm("ex2.approx.ftz.f32 %0, %1;" : "=f"(y) : "f"(x)); return y;
}
// bf16 hi/lo split of two floats, packed bf16x2 (first value in low half)
__device__ __forceinline__ void split2(float x0, float x1, uint32_t& hp, uint32_t& lp) {
    __nv_bfloat16 h0 = __float2bfloat16(x0), h1 = __float2bfloat16(x1);
    float l0 = x0 - __bfloat162float(h0), l1 = x1 - __bfloat162float(h1);
    hp = ((uint32_t)__bfloat16_as_ushort(h1) << 16) | (uint32_t)__bfloat16_as_ushort(h0);
    __nv_bfloat162 lb = __floats2bfloat162_rn(l0, l1);
    lp = *reinterpret_cast<uint32_t*>(&lb);
}
__device__ __forceinline__ uint32_t packh2(float x0, float x1) {
    __half2 h = __floats2half2_rn(x0, x1);
    return *reinterpret_cast<uint32_t*>(&h);
}

// bf16 x bf16 MMA
__device__ __forceinline__ void mma16816(float* c, const uint32_t* a, const uint32_t* b) {
    asm volatile(
        "mma.sync.aligned.m16n8k16.row.col.f32.bf16.bf16.f32 "
        "{%0,%1,%2,%3}, {%4,%5,%6,%7}, {%8,%9}, {%0,%1,%2,%3};"
        : "+f"(c[0]), "+f"(c[1]), "+f"(c[2]), "+f"(c[3])
        : "r"(a[0]), "r"(a[1]), "r"(a[2]), "r"(a[3]), "r"(b[0]), "r"(b[1]));
}
// fp16 x fp16 MMA
__device__ __forceinline__ void mma16816h(float* c, const uint32_t* a, const uint32_t* b) {
    asm volatile(
        "mma.sync.aligned.m16n8k16.row.col.f32.f16.f16.f32 "
        "{%0,%1,%2,%3}, {%4,%5,%6,%7}, {%8,%9}, {%0,%1,%2,%3};"
        : "+f"(c[0]), "+f"(c[1]), "+f"(c[2]), "+f"(c[3])
        : "r"(a[0]), "r"(a[1]), "r"(a[2]), "r"(a[3]), "r"(b[0]), "r"(b[1]));
}
__device__ __forceinline__ void ldsm4(uint32_t* r, uint32_t addr) {
    asm volatile("ldmatrix.sync.aligned.m8n8.x4.shared.b16 {%0,%1,%2,%3}, [%4];"
                 : "=r"(r[0]), "=r"(r[1]), "=r"(r[2]), "=r"(r[3]) : "r"(addr));
}
__device__ __forceinline__ void ldsm4t(uint32_t* r, uint32_t addr) {
    asm volatile("ldmatrix.sync.aligned.m8n8.x4.trans.shared.b16 {%0,%1,%2,%3}, [%4];"
                 : "=r"(r[0]), "=r"(r[1]), "=r"(r[2]), "=r"(r[3]) : "r"(addr));
}

// ---------------- pre-kernel: K -> bf16 hi/lo, V -> fp16; [b][n][h][d] -> [b][h][n][d] ----------------
__global__ void __launch_bounds__(256)
conv_kv(const float* __restrict__ K, const float* __restrict__ V)
{
    int idx = blockIdx.x * 256 + threadIdx.x;     // 262144 total
    int dc = idx & 7;                             // 8-elem d chunk
    int n  = (idx >> 3) & (N_ - 1);
    int h  = (idx >> 14) & (H_ - 1);
    int b  = idx >> 17;
    size_t src = (((size_t)(b * N_ + n) * H_ + h) * D_) + dc * 8;
    size_t dst = (((size_t)(b * H_ + h) * N_ + n) * D_) + dc * 8;

    float4 k0 = *reinterpret_cast<const float4*>(K + src);
    float4 k1 = *reinterpret_cast<const float4*>(K + src + 4);
    float4 v0 = *reinterpret_cast<const float4*>(V + src);
    float4 v1 = *reinterpret_cast<const float4*>(V + src + 4);

    uint4 kh, kl;
    split2(k0.x, k0.y, kh.x, kl.x); split2(k0.z, k0.w, kh.y, kl.y);
    split2(k1.x, k1.y, kh.z, kl.z); split2(k1.z, k1.w, kh.w, kl.w);

    uint4 vf;
    vf.x = packh2(v0.x, v0.y); vf.y = packh2(v0.z, v0.w);
    vf.z = packh2(v1.x, v1.y); vf.w = packh2(v1.z, v1.w);

    *reinterpret_cast<uint4*>(g_kh + dst) = kh;
    *reinterpret_cast<uint4*>(g_kl + dst) = kl;
    *reinterpret_cast<uint4*>(g_vf + dst) = vf;
}

// ---------------- main kernel (round-14 skeleton; PV = single-pass fp16) ----------------
__global__ void __launch_bounds__(THREADS, 1)
diff_attn_hmma(const float* __restrict__ Q,
               const float* __restrict__ lq1, const float* __restrict__ lk1,
               const float* __restrict__ lq2, const float* __restrict__ lk2,
               float* __restrict__ out)
{
    extern __shared__ __align__(128) char sm[];
    const uint32_t sb = s2u(sm);
    const int tid = threadIdx.x;
    const int wid = tid >> 5, lane = tid & 31;
    const int qb = blockIdx.x, h = blockIdx.y, b = blockIdx.z;
    const int qi0 = qb * BQ;

    // ---- lambda (warp 2) ----
    if (wid == 2) {
        float p1 = lq1[lane] * lk1[lane] + lq1[lane + 32] * lk1[lane + 32];
        float p2 = lq2[lane] * lk2[lane] + lq2[lane + 32] * lk2[lane + 32];
        #pragma unroll
        for (int o = 16; o; o >>= 1) {
            p1 += __shfl_xor_sync(0xffffffffu, p1, o);
            p2 += __shfl_xor_sync(0xffffffffu, p2, o);
        }
        if (lane == 0)
            *reinterpret_cast<float*>(sm) = __expf(p1) - __expf(p2) + LAMBDA_INIT_F;
    }

    // ---- stage Q (128 rows: 64 top | 64 bottom), scaled, bf16 hi/lo ----
    {
        int row = tid & 127, d0 = (tid >> 7) * 32;
        int qi = qi0 + ((row < BQ) ? row : row - BQ + NO_);
        const float4* qp = reinterpret_cast<const float4*>(
            Q + ((size_t)(b * N_ + qi) * H_ + h) * D_ + d0);
        float x[32];
        #pragma unroll
        for (int i = 0; i < 8; ++i) {
            float4 f = qp[i];
            x[4*i]   = f.x * QSCALE; x[4*i+1] = f.y * QSCALE;
            x[4*i+2] = f.z * QSCALE; x[4*i+3] = f.w * QSCALE;
        }
        uint32_t rb = (uint32_t)row * 128;
        #pragma unroll
        for (int j = 0; j < 8; ++j) {
            uint32_t h0, l0, h1, l1;
            split2(x[4*j], x[4*j+1], h0, l0);
            split2(x[4*j+2], x[4*j+3], h1, l1);
            uint32_t off = swz(rb + (uint32_t)(d0 + 4*j) * 2);
            *reinterpret_cast<uint2*>(sm + OFF_QH + off) = make_uint2(h0, h1);
            *reinterpret_cast<uint2*>(sm + OFF_QL + off) = make_uint2(l0, l1);
        }
    }

    // ---- K/V staging: thread owns (key = tid&63, d = kd0..kd0+15) ----
    const int key = tid & 63, kd0 = (tid >> 6) * 16;
    const size_t kvbase = ((size_t)(b * H_ + h) * N_ + key) * D_ + kd0;
    constexpr size_t TSTRIDE = (size_t)BK * D_;

    uint32_t soff2[2];
    #pragma unroll
    for (int j = 0; j < 2; ++j)
        soff2[j] = swz((uint32_t)key * 128 + (uint32_t)(kd0 * 2 + j * 16));

    uint4 skh[2], skl[2], svf[2];
    #pragma unroll
    for (int j = 0; j < 2; ++j) {
        skh[j] = *reinterpret_cast<const uint4*>(g_kh + kvbase + j * 8);
        skl[j] = *reinterpret_cast<const uint4*>(g_kl + kvbase + j * 8);
        svf[j] = *reinterpret_cast<const uint4*>(g_vf + kvbase + j * 8);
    }
    #pragma unroll
    for (int j = 0; j < 2; ++j) {
        *reinterpret_cast<uint4*>(sm + OFF_KH + soff2[j]) = skh[j];
        *reinterpret_cast<uint4*>(sm + OFF_KL + soff2[j]) = skl[j];
        *reinterpret_cast<uint4*>(sm + OFF_VF + soff2[j]) = svf[j];
    }
    __syncthreads();

    // ---- lane geometry ----
    const int grp = lane >> 3, rr = lane & 7;
    const int rowsel = (grp & 1) * 8 + rr;
    const int colsel = (grp >> 1) * 8;
    const int g = lane >> 2, q = lane & 3;

    // ---- persistent Q fragments ----
    uint32_t qh[4][4], ql[4][4];
    #pragma unroll
    for (int ks = 0; ks < 4; ++ks) {
        uint32_t off = swz((uint32_t)((wid * 16 + rowsel) << 7) +
                           (uint32_t)((ks * 16 + colsel) << 1));
        ldsm4(qh[ks], sb + OFF_QH + off);
        ldsm4(ql[ks], sb + OFF_QL + off);
    }

    float oC[8][4];
    #pragma unroll
    for (int f = 0; f < 8; ++f)
        #pragma unroll
        for (int i = 0; i < 4; ++i) oC[f][i] = 0.f;
    float l0 = 0.f, l1 = 0.f;

    // =========================== mainloop ===========================
    for (int t = 0; t < TILES; ++t) {
        const bool pre = (t + 1 < TILES);
        if (pre) {
            size_t gk = kvbase + (size_t)(t + 1) * TSTRIDE;
            #pragma unroll
            for (int j = 0; j < 2; ++j) {
                skh[j] = *reinterpret_cast<const uint4*>(g_kh + gk + j * 8);
                skl[j] = *reinterpret_cast<const uint4*>(g_kl + gk + j * 8);
            }
        }

        // ---- S = Q Kt^T (3 compensated passes, pass-major) ----
        float sC[8][4];
        #pragma unroll
        for (int f = 0; f < 8; ++f)
            #pragma unroll
            for (int i = 0; i < 4; ++i) sC[f][i] = 0.f;

        #pragma unroll
        for (int ks = 0; ks < 4; ++ks) {
            uint32_t kh[16], kl[16];
            #pragma unroll
            for (int fp = 0; fp < 4; ++fp) {
                uint32_t off = swz((uint32_t)((fp * 16 + rowsel) << 7) +
                                   (uint32_t)((ks * 16 + colsel) << 1));
                uint32_t r4[4];
                ldsm4(r4, sb + OFF_KH + off);
                kh[4*fp] = r4[0]; kh[4*fp+1] = r4[2]; kh[4*fp+2] = r4[1]; kh[4*fp+3] = r4[3];
                ldsm4(r4, sb + OFF_KL + off);
                kl[4*fp] = r4[0]; kl[4*fp+1] = r4[2]; kl[4*fp+2] = r4[1]; kl[4*fp+3] = r4[3];
            }
            #pragma unroll
            for (int f = 0; f < 8; ++f) mma16816(sC[f], qh[ks], &kh[2*f]);
            #pragma unroll
            for (int f = 0; f < 8; ++f) mma16816(sC[f], qh[ks], &kl[2*f]);
            #pragma unroll
            for (int f = 0; f < 8; ++f) mma16816(sC[f], ql[ks], &kh[2*f]);
        }

        // ---- softmax (base-2, no max: logits bounded) ----
        float p[8][4];
        #pragma unroll
        for (int f = 0; f < 8; ++f) {
            p[f][0] = ex2(sC[f][0]); p[f][1] = ex2(sC[f][1]);
            p[f][2] = ex2(sC[f][2]); p[f][3] = ex2(sC[f][3]);
            l0 += p[f][0] + p[f][1];
            l1 += p[f][2] + p[f][3];
        }
        // P accum frags -> fp16 A frags (single precision level)
        uint32_t pf[4][4];
        #pragma unroll
        for (int kk = 0; kk < 4; ++kk) {
            int f0 = 2 * kk, f1 = f0 + 1;
            pf[kk][0] = packh2(p[f0][0], p[f0][1]);
            pf[kk][1] = packh2(p[f0][2], p[f0][3]);
            pf[kk][2] = packh2(p[f1][0], p[f1][1]);
            pf[kk][3] = packh2(p[f1][2], p[f1][3]);
        }

        if (pre) {
            size_t gv = kvbase + (size_t)(t + 1) * TSTRIDE;
            #pragma unroll
            for (int j = 0; j < 2; ++j)
                svf[j] = *reinterpret_cast<const uint4*>(g_vf + gv + j * 8);
        }

        // ---- O += P V (single fp16 pass) ----
        #pragma unroll
        for (int ks = 0; ks < 4; ++ks) {
            uint32_t vf[16];
            #pragma unroll
            for (int dp = 0; dp < 4; ++dp) {
                uint32_t off = swz((uint32_t)((ks * 16 + rowsel) << 7) +
                                   (uint32_t)((dp * 16 + colsel) << 1));
                uint32_t r4[4];
                ldsm4t(r4, sb + OFF_VF + off);
                vf[4*dp] = r4[0]; vf[4*dp+1] = r4[1]; vf[4*dp+2] = r4[2]; vf[4*dp+3] = r4[3];
            }
            #pragma unroll
            for (int f = 0; f < 8; ++f) mma16816h(oC[f], pf[ks], &vf[2*f]);
        }

        if (pre) {
            __syncthreads();   // all warps done reading tile t
            #pragma unroll
            for (int j = 0; j < 2; ++j) {
                *reinterpret_cast<uint4*>(sm + OFF_KH + soff2[j]) = skh[j];
                *reinterpret_cast<uint4*>(sm + OFF_KL + soff2[j]) = skl[j];
                *reinterpret_cast<uint4*>(sm + OFF_VF + soff2[j]) = svf[j];
            }
            __syncthreads();
        }
    }

    // ---- row-sum reduce across the 4 lanes sharing a row ----
    l0 += __shfl_xor_sync(0xffffffffu, l0, 1);
    l0 += __shfl_xor_sync(0xffffffffu, l0, 2);
    l1 += __shfl_xor_sync(0xffffffffu, l1, 1);
    l1 += __shfl_xor_sync(0xffffffffu, l1, 2);

    __syncthreads();   // everyone done with smem tiles before staging overwrites

    // ---- normalize + stage O to smem ----
    {
        float inv0 = 1.f / l0, inv1 = 1.f / l1;
        float* stg = reinterpret_cast<float*>(sm + 1024);
        int r0 = wid * 16 + g, r1 = r0 + 8;
        #pragma unroll
        for (int f = 0; f < 8; ++f) {
            int col = 8 * f + 2 * q;
            stg[r0 * STG_LD + col]     = oC[f][0] * inv0;
            stg[r0 * STG_LD + col + 1] = oC[f][1] * inv0;
            stg[r1 * STG_LD + col]     = oC[f][2] * inv1;
            stg[r1 * STG_LD + col + 1] = oC[f][3] * inv1;
        }
    }
    __syncthreads();

    // ---- combine top - lambda*bottom, write out ----
    {
        const float lam = *reinterpret_cast<const float*>(sm);
        const float* stg = reinterpret_cast<const float*>(sm + 1024);
        #pragma unroll
        for (int it = 0; it < 4; ++it) {
            int slot = it * THREADS + tid;
            int r = slot >> 4, c4 = (slot & 15) << 2;
            float4 tp = *reinterpret_cast<const float4*>(stg + (size_t)r * STG_LD + c4);
            float4 bt = *reinterpret_cast<const float4*>(stg + (size_t)(r + BQ) * STG_LD + c4);
            float4 res;
            res.x = tp.x - lam * bt.x; res.y = tp.y - lam * bt.y;
            res.z = tp.z - lam * bt.z; res.w = tp.w - lam * bt.w;
            *reinterpret_cast<float4*>(
                out + ((size_t)((b * H_ + h) * NO_) + qi0 + r) * D_ + c4) = res;
        }
    }
}

}  // namespace

extern "C" void kernel_launch(void* const* d_in, const int* in_sizes, int n_in,
                              void* d_out, int out_size)
{
    (void)in_sizes; (void)n_in; (void)out_size;
    const float* q   = (const float*)d_in[0];
    const float* k   = (const float*)d_in[1];
    const float* v   = (const float*)d_in[2];
    const float* lq1 = (const float*)d_in[3];
    const float* lk1 = (const float*)d_in[4];
    const float* lq2 = (const float*)d_in[5];
    const float* lk2 = (const float*)d_in[6];
    float* out = (float*)d_out;

    conv_kv<<<1024, 256>>>(k, v);   // K -> bf16 hi/lo, V -> fp16; [b][h][n][d]

    cudaFuncSetAttribute(diff_attn_hmma,
                         cudaFuncAttributeMaxDynamicSharedMemorySize, SMEM_TOTAL);
    dim3 grid(NO_ / BQ, H_, B_);    // (16, 8, 2) = 256 CTAs
    diff_attn_hmma<<<grid, THREADS, SMEM_TOTAL>>>(q, lq1, lk1, lq2, lk2, out);
}